// round 9
// baseline (speedup 1.0000x reference)
#include <cuda_runtime.h>
#include <cuda_fp16.h>
#include <math.h>
#include <stdint.h>

#define T_TOK 4096
#define HDIM 1024
#define FDIM 512
#define NEXP 8
#define MAXP 4096
#define MAXTILE 96
#define WELEM (NEXP * HDIM * FDIM)

// ---------------- device scratch ----------------
__device__ int    g_cnt[NEXP];
__device__ int    g_off[NEXP];
__device__ int    g_tok[NEXP * MAXP];
__device__ float  g_wt [NEXP * MAXP];
__device__ int    g_pair[T_TOK * 2];
__device__ int    g_tbl[MAXTILE];
__device__ int    g_ntile;
__device__ __half g_xh  [T_TOK * HDIM];
__device__ __half g_acth[T_TOK * 2 * FDIM];
__device__ float  g_dout[T_TOK * 2 * HDIM];
__device__ __half g_wgh[WELEM];
__device__ __half g_wuh[WELEM];
__device__ __half g_wdh[WELEM];

#define MMA16(c, a0, a1, a2, a3, b0, b1) \
    asm volatile("mma.sync.aligned.m16n8k16.row.col.f32.f16.f16.f32 " \
        "{%0,%1,%2,%3},{%4,%5,%6,%7},{%8,%9},{%0,%1,%2,%3};" \
        : "+f"((c)[0]), "+f"((c)[1]), "+f"((c)[2]), "+f"((c)[3]) \
        : "r"(a0), "r"(a1), "r"(a2), "r"(a3), "r"(b0), "r"(b1))

#define LDSM4(r, addr) \
    asm volatile("ldmatrix.sync.aligned.m8n8.x4.shared.b16 {%0,%1,%2,%3}, [%4];" \
        : "=r"((r)[0]), "=r"((r)[1]), "=r"((r)[2]), "=r"((r)[3]) : "r"(addr))
#define LDSM4T(r, addr) \
    asm volatile("ldmatrix.sync.aligned.m8n8.x4.trans.shared.b16 {%0,%1,%2,%3}, [%4];" \
        : "=r"((r)[0]), "=r"((r)[1]), "=r"((r)[2]), "=r"((r)[3]) : "r"(addr))

__device__ __forceinline__ void cpa16(uint32_t s, const void* g) {
    asm volatile("cp.async.cg.shared.global [%0], [%1], 16;" :: "r"(s), "l"(g));
}
#define CPCOMMIT() asm volatile("cp.async.commit_group;")
#define CPWAIT1()  asm volatile("cp.async.wait_group 1;" ::: "memory")

__device__ __forceinline__ uint32_t smem_u32(const void* p) {
    uint32_t a;
    asm("{ .reg .u64 t; cvta.to.shared.u64 t, %1; cvt.u32.u64 %0, t; }" : "=r"(a) : "l"(p));
    return a;
}

// stage: A 16KB ([c 0..7][m 0..127] x 16B) + B 16KB ([cb 0..15][k 0..63] x 16B)
#define STGB 32768
#define NSTG 3
#define GEMM_SMEM (NSTG * STGB + 1024)

// ---------------- tiny setup ----------------
__global__ void zero_cnt_kernel() { if (threadIdx.x < NEXP) g_cnt[threadIdx.x] = 0; }
__global__ void scan_kernel() {
    if (threadIdx.x == 0) {
        int o = 0, nt = 0;
        for (int e = 0; e < NEXP; e++) {
            g_off[e] = o;
            int c = g_cnt[e];
            for (int m0 = 0; m0 < c; m0 += 128) g_tbl[nt++] = (e << 12) | m0;
            o += c;
        }
        g_ntile = nt;
    }
}

// ---------------- weight fp32 -> fp16 ----------------
__global__ __launch_bounds__(256) void wconv_kernel(
    const float* __restrict__ Wg, const float* __restrict__ Wu,
    const float* __restrict__ Wd)
{
    int seg = blockIdx.y;
    size_t i = ((size_t)blockIdx.x * 256 + threadIdx.x) * 4;
    const float* s = (seg == 0) ? Wg : (seg == 1) ? Wu : Wd;
    __half* d = (seg == 0) ? g_wgh : (seg == 1) ? g_wuh : g_wdh;
    float4 v = *(const float4*)(s + i);
    __half2 lo = __floats2half2_rn(v.x, v.y);
    __half2 hi = __floats2half2_rn(v.z, v.w);
    *(uint2*)(d + i) = make_uint2(*(uint32_t*)&lo, *(uint32_t*)&hi);
}

// ---------------- router (fp32-exact) + x->fp16 ----------------
__global__ __launch_bounds__(128) void router_kernel(
    const float* __restrict__ x, const float* __restrict__ Wr)
{
    int t = blockIdx.x * 4 + (threadIdx.x >> 5);
    int lane = threadIdx.x & 31;
    const float* xr = x + (size_t)t * HDIM;
    float acc[NEXP];
#pragma unroll
    for (int e = 0; e < NEXP; e++) acc[e] = 0.0f;
    for (int h = lane; h < HDIM; h += 32) {
        float xv = xr[h];
        g_xh[(size_t)t * HDIM + h] = __float2half_rn(xv);
        const float4* wr4 = (const float4*)(Wr + (size_t)h * NEXP);
        float4 w0 = wr4[0], w1 = wr4[1];
        acc[0] = fmaf(xv, w0.x, acc[0]); acc[1] = fmaf(xv, w0.y, acc[1]);
        acc[2] = fmaf(xv, w0.z, acc[2]); acc[3] = fmaf(xv, w0.w, acc[3]);
        acc[4] = fmaf(xv, w1.x, acc[4]); acc[5] = fmaf(xv, w1.y, acc[5]);
        acc[6] = fmaf(xv, w1.z, acc[6]); acc[7] = fmaf(xv, w1.w, acc[7]);
    }
#pragma unroll
    for (int e = 0; e < NEXP; e++)
#pragma unroll
        for (int o = 16; o > 0; o >>= 1)
            acc[e] += __shfl_xor_sync(0xFFFFFFFFu, acc[e], o);
    if (lane == 0) {
        float m = acc[0];
#pragma unroll
        for (int e = 1; e < NEXP; e++) m = fmaxf(m, acc[e]);
        float p[NEXP];
#pragma unroll
        for (int e = 0; e < NEXP; e++) p[e] = expf(acc[e] - m);
        int i0 = 0;
#pragma unroll
        for (int e = 1; e < NEXP; e++) if (p[e] > p[i0]) i0 = e;
        int i1 = (i0 == 0) ? 1 : 0;
#pragma unroll
        for (int e = 0; e < NEXP; e++) if (e != i0 && p[e] > p[i1]) i1 = e;
        float s = p[i0] + p[i1];
        int p0 = atomicAdd(&g_cnt[i0], 1);
        g_tok[i0 * MAXP + p0] = t; g_wt[i0 * MAXP + p0] = p[i0] / s;
        g_pair[t * 2 + 0] = i0 * MAXP + p0;
        int p1 = atomicAdd(&g_cnt[i1], 1);
        g_tok[i1 * MAXP + p1] = t; g_wt[i1 * MAXP + p1] = p[i1] / s;
        g_pair[t * 2 + 1] = i1 * MAXP + p1;
    }
}

// =====================================================================
// gate+up GEMM + SwiGLU. Block 128m x 128n' (8-col chunks alternate
// gate/up), BK=64, 256 threads, 8 warps (2m x 4n), warp 64x32.
// cp.async 3-stage ring, ldmatrix fragments.
// =====================================================================
__global__ __launch_bounds__(256, 2) void mg_gateup()
{
    extern __shared__ char smraw[];
    uint32_t sb = smem_u32(smraw);
    int tile = blockIdx.x;
    if (tile >= g_ntile) return;
    int pk = g_tbl[tile];
    int e = pk >> 12, m0 = pk & 4095;
    int cnt = g_cnt[e];
    int f0 = blockIdx.y * 64;

    int tid = threadIdx.x, lane = tid & 31, wid = tid >> 5;
    int wmi = wid >> 2, wni = wid & 3;
    int lr = lane >> 2, l3 = lane & 3;

    int*   stok = (int*)(smraw + NSTG * STGB);
    float* swt  = (float*)(smraw + NSTG * STGB + 512);
    if (tid < 128) {
        int r = m0 + tid, rc = min(r, cnt - 1);
        stok[tid] = g_tok[e * MAXP + rc];
        swt[tid]  = (r < cnt) ? g_wt[e * MAXP + rc] : 0.0f;
    }
    __syncthreads();

    // A cp.async: am row, chunks aq, aq+2, aq+4, aq+6 (chunk c = 8 k)
    int am = tid & 127, aq = tid >> 7;
    const __half* arow = g_xh + (size_t)stok[am] * HDIM + aq * 8;
    // B cp.async: k = tid&63, chunks cq, cq+4, cq+8, cq+12
    int bk = tid & 63, cq = tid >> 6;
    const __half* wsel = ((cq & 1) ? g_wuh : g_wgh) + (size_t)e * HDIM * FDIM
                        + (size_t)bk * FDIM + f0 + (cq >> 1) * 8;

    auto ISSUE = [&](int s) {
        int kb = s * 64;
        uint32_t Ab = sb + (s % NSTG) * STGB;
        uint32_t Bb = Ab + 16384;
#pragma unroll
        for (int j = 0; j < 4; j++)
            cpa16(Ab + (((aq + j * 2) * 128) + am) * 16, arow + kb + j * 16);
#pragma unroll
        for (int j = 0; j < 4; j++)
            cpa16(Bb + (((cq + j * 4) * 64) + bk) * 16,
                  wsel + (size_t)kb * FDIM + j * 16);
    };

    float c[4][4][4];
#pragma unroll
    for (int a = 0; a < 4; a++)
#pragma unroll
        for (int b = 0; b < 4; b++)
#pragma unroll
            for (int k = 0; k < 4; k++) c[a][b][k] = 0.0f;

    const int NS = HDIM / 64;   // 16 stages
    ISSUE(0); CPCOMMIT();
    ISSUE(1); CPCOMMIT();

    uint32_t aoff = (uint32_t)((lane >> 4) * 128 + wmi * 64 + (lane & 15)) * 16;
    uint32_t boff = (uint32_t)((wni * 4 + (lane >> 4)) * 64 + (lane & 15)) * 16;

    for (int s = 0; s < NS; s++) {
        CPWAIT1();
        __syncthreads();
        if (s + 2 < NS) ISSUE(s + 2);
        CPCOMMIT();
        uint32_t Ab = sb + (s % NSTG) * STGB;
        uint32_t Bb = Ab + 16384;
#pragma unroll
        for (int kk = 0; kk < 4; kk++) {
            uint32_t a[4][4], b[2][4];
#pragma unroll
            for (int mt = 0; mt < 4; mt++)
                LDSM4(a[mt], Ab + aoff + (kk * 2 * 128 + mt * 16) * 16);
#pragma unroll
            for (int bt = 0; bt < 2; bt++)
                LDSM4T(b[bt], Bb + boff + (bt * 2 * 64 + kk * 16) * 16);
#pragma unroll
            for (int nt = 0; nt < 4; nt++) {
                uint32_t b0 = b[nt >> 1][(nt & 1) * 2], b1 = b[nt >> 1][(nt & 1) * 2 + 1];
#pragma unroll
                for (int mt = 0; mt < 4; mt++)
                    MMA16(c[mt][nt], a[mt][0], a[mt][1], a[mt][2], a[mt][3], b0, b1);
            }
        }
    }

    // epilogue: nt even = gate, nt odd = up
    int gbase = g_off[e];
#pragma unroll
    for (int mt = 0; mt < 4; mt++)
#pragma unroll
        for (int rr = 0; rr < 2; rr++) {
            int row = wmi * 64 + mt * 16 + lr + rr * 8;
            if (m0 + row < cnt) {
                float w = swt[row];
                __half* dst = g_acth + (size_t)(gbase + m0 + row) * FDIM + f0 + wni * 16 + 2 * l3;
#pragma unroll
                for (int j = 0; j < 2; j++) {
                    float gv0 = c[mt][2 * j][rr * 2],     gv1 = c[mt][2 * j][rr * 2 + 1];
                    float uv0 = c[mt][2 * j + 1][rr * 2], uv1 = c[mt][2 * j + 1][rr * 2 + 1];
                    float o0 = w * (gv0 / (1.0f + expf(-gv0))) * uv0;
                    float o1 = w * (gv1 / (1.0f + expf(-gv1))) * uv1;
                    *(__half2*)(dst + j * 8) = __floats2half2_rn(o0, o1);
                }
            }
        }
}

// =====================================================================
// down GEMM. Block 128m x 128h, BK=64, 256 threads, warp 64x32.
// =====================================================================
__global__ __launch_bounds__(256, 2) void mg_down()
{
    extern __shared__ char smraw[];
    uint32_t sb = smem_u32(smraw);
    int tile = blockIdx.x;
    if (tile >= g_ntile) return;
    int pk = g_tbl[tile];
    int e = pk >> 12, m0 = pk & 4095;
    int cnt = g_cnt[e];
    int h0 = blockIdx.y * 128;

    int tid = threadIdx.x, lane = tid & 31, wid = tid >> 5;
    int wmi = wid >> 2, wni = wid & 3;
    int lr = lane >> 2, l3 = lane & 3;
    int gbase = g_off[e];

    int am = tid & 127, aq = tid >> 7;
    const __half* arow = g_acth + (size_t)(gbase + min(m0 + am, cnt - 1)) * FDIM + aq * 8;
    int bk = tid & 63, cq = tid >> 6;
    const __half* wsel = g_wdh + (size_t)e * FDIM * HDIM + (size_t)bk * HDIM + h0 + cq * 8;

    auto ISSUE = [&](int s) {
        int kb = s * 64;
        uint32_t Ab = sb + (s % NSTG) * STGB;
        uint32_t Bb = Ab + 16384;
#pragma unroll
        for (int j = 0; j < 4; j++)
            cpa16(Ab + (((aq + j * 2) * 128) + am) * 16, arow + kb + j * 16);
#pragma unroll
        for (int j = 0; j < 4; j++)
            cpa16(Bb + (((cq + j * 4) * 64) + bk) * 16,
                  wsel + (size_t)kb * HDIM + j * 32);
    };

    float c[4][4][4];
#pragma unroll
    for (int a = 0; a < 4; a++)
#pragma unroll
        for (int b = 0; b < 4; b++)
#pragma unroll
            for (int k = 0; k < 4; k++) c[a][b][k] = 0.0f;

    const int NS = FDIM / 64;   // 8 stages
    ISSUE(0); CPCOMMIT();
    ISSUE(1); CPCOMMIT();

    uint32_t aoff = (uint32_t)((lane >> 4) * 128 + wmi * 64 + (lane & 15)) * 16;
    uint32_t boff = (uint32_t)((wni * 4 + (lane >> 4)) * 64 + (lane & 15)) * 16;

    for (int s = 0; s < NS; s++) {
        CPWAIT1();
        __syncthreads();
        if (s + 2 < NS) ISSUE(s + 2);
        CPCOMMIT();
        uint32_t Ab = sb + (s % NSTG) * STGB;
        uint32_t Bb = Ab + 16384;
#pragma unroll
        for (int kk = 0; kk < 4; kk++) {
            uint32_t a[4][4], b[2][4];
#pragma unroll
            for (int mt = 0; mt < 4; mt++)
                LDSM4(a[mt], Ab + aoff + (kk * 2 * 128 + mt * 16) * 16);
#pragma unroll
            for (int bt = 0; bt < 2; bt++)
                LDSM4T(b[bt], Bb + boff + (bt * 2 * 64 + kk * 16) * 16);
#pragma unroll
            for (int nt = 0; nt < 4; nt++) {
                uint32_t b0 = b[nt >> 1][(nt & 1) * 2], b1 = b[nt >> 1][(nt & 1) * 2 + 1];
#pragma unroll
                for (int mt = 0; mt < 4; mt++)
                    MMA16(c[mt][nt], a[mt][0], a[mt][1], a[mt][2], a[mt][3], b0, b1);
            }
        }
    }

#pragma unroll
    for (int mt = 0; mt < 4; mt++)
#pragma unroll
        for (int rr = 0; rr < 2; rr++) {
            int row = wmi * 64 + mt * 16 + lr + rr * 8;
            if (m0 + row < cnt) {
                float* dst = g_dout + (size_t)(gbase + m0 + row) * HDIM + h0 + wni * 32 + 2 * l3;
#pragma unroll
                for (int nt = 0; nt < 4; nt++)
                    *(float2*)(dst + nt * 8) =
                        make_float2(c[mt][nt][rr * 2], c[mt][nt][rr * 2 + 1]);
            }
        }
}

// ---------------- combine ----------------
__global__ __launch_bounds__(256) void combine_kernel(float* __restrict__ out)
{
    int idx = blockIdx.x * blockDim.x + threadIdx.x;
    int t = idx >> 8;
    int hq = (idx & 255) * 4;
    int v0 = g_pair[t * 2 + 0], v1 = g_pair[t * 2 + 1];
    int gi0 = g_off[v0 >> 12] + (v0 & (MAXP - 1));
    int gi1 = g_off[v1 >> 12] + (v1 & (MAXP - 1));
    float4 a = *(const float4*)(g_dout + (size_t)gi0 * HDIM + hq);
    float4 b = *(const float4*)(g_dout + (size_t)gi1 * HDIM + hq);
    float4 o = {a.x + b.x, a.y + b.y, a.z + b.z, a.w + b.w};
    *(float4*)(out + (size_t)t * HDIM + hq) = o;
}

// ---------------- launch ----------------
extern "C" void kernel_launch(void* const* d_in, const int* in_sizes, int n_in,
                              void* d_out, int out_size)
{
    const float* x  = (const float*)d_in[0];
    const float* Wr = (const float*)d_in[1];
    const float* Wg = (const float*)d_in[2];
    const float* Wu = (const float*)d_in[3];
    const float* Wd = (const float*)d_in[4];
    float* out = (float*)d_out;

    cudaFuncSetAttribute(mg_gateup, cudaFuncAttributeMaxDynamicSharedMemorySize, GEMM_SMEM);
    cudaFuncSetAttribute(mg_down,   cudaFuncAttributeMaxDynamicSharedMemorySize, GEMM_SMEM);

    zero_cnt_kernel<<<1, 32>>>();
    wconv_kernel<<<dim3(WELEM / 1024, 3), 256>>>(Wg, Wu, Wd);
    router_kernel<<<T_TOK / 4, 128>>>(x, Wr);
    scan_kernel<<<1, 32>>>();

    dim3 gg(72, FDIM / 64);
    mg_gateup<<<gg, 256, GEMM_SMEM>>>();

    dim3 gd(72, HDIM / 128);
    mg_down<<<gd, 256, GEMM_SMEM>>>();

    combine_kernel<<<(T_TOK * HDIM / 4) / 256, 256>>>(out);
}

// round 10
// speedup vs baseline: 1.0381x; 1.0381x over previous
#include <cuda_runtime.h>
#include <cuda_fp16.h>
#include <math.h>
#include <stdint.h>

#define T_TOK 4096
#define HDIM 1024
#define FDIM 512
#define NEXP 8
#define MAXP 4096
#define WELEM (NEXP * HDIM * FDIM)

// ---------------- device scratch ----------------
__device__ int    g_cnt[NEXP];
__device__ int    g_tok[NEXP * MAXP];
__device__ float  g_wt [NEXP * MAXP];
__device__ int    g_pair[T_TOK * 2];
__device__ __half g_xh  [T_TOK * HDIM];
__device__ __half g_acth[T_TOK * 2 * FDIM];
__device__ float  g_dout[T_TOK * 2 * HDIM];
__device__ __half g_wgh[WELEM];
__device__ __half g_wuh[WELEM];
__device__ __half g_wdh[WELEM];

#define MMA16(c, a0, a1, a2, a3, b0, b1) \
    asm volatile("mma.sync.aligned.m16n8k16.row.col.f32.f16.f16.f32 " \
        "{%0,%1,%2,%3},{%4,%5,%6,%7},{%8,%9},{%0,%1,%2,%3};" \
        : "+f"((c)[0]), "+f"((c)[1]), "+f"((c)[2]), "+f"((c)[3]) \
        : "r"(a0), "r"(a1), "r"(a2), "r"(a3), "r"(b0), "r"(b1))

#define LDSM4(r, addr) \
    asm volatile("ldmatrix.sync.aligned.m8n8.x4.shared.b16 {%0,%1,%2,%3}, [%4];" \
        : "=r"((r)[0]), "=r"((r)[1]), "=r"((r)[2]), "=r"((r)[3]) : "r"(addr))
#define LDSM4T(r, addr) \
    asm volatile("ldmatrix.sync.aligned.m8n8.x4.trans.shared.b16 {%0,%1,%2,%3}, [%4];" \
        : "=r"((r)[0]), "=r"((r)[1]), "=r"((r)[2]), "=r"((r)[3]) : "r"(addr))

__device__ __forceinline__ void cpa16(uint32_t s, const void* g) {
    asm volatile("cp.async.cg.shared.global [%0], [%1], 16;" :: "r"(s), "l"(g));
}
#define CPCOMMIT() asm volatile("cp.async.commit_group;")
#define CPWAIT2()  asm volatile("cp.async.wait_group 2;" ::: "memory")

__device__ __forceinline__ uint32_t smem_u32(const void* p) {
    uint32_t a;
    asm("{ .reg .u64 t; cvta.to.shared.u64 t, %1; cvt.u32.u64 %0, t; }" : "=r"(a) : "l"(p));
    return a;
}

// map flat tile -> (expert, m0, gbase, cnt); tiles are 128 rows
__device__ __forceinline__ bool tile_map(int tile, int& e, int& m0, int& gbase, int& cnt) {
    int acc = 0, off = 0;
#pragma unroll
    for (int i = 0; i < NEXP; i++) {
        int c = g_cnt[i];
        int nt = (c + 127) >> 7;
        if (tile < acc + nt) { e = i; m0 = (tile - acc) << 7; gbase = off; cnt = c; return true; }
        acc += nt; off += c;
    }
    return false;
}

// stage: A 8KB ([c 0..3][m 0..127] x 16B) + B 8KB ([cb 0..15][k 0..31] x 16B)
#define STGB 16384
#define GEMM_SMEM (4 * STGB + 1024)

// ---------------- weight fp32 -> fp16 (+ counter zeroing) ----------------
__global__ __launch_bounds__(256) void wconv_kernel(
    const float* __restrict__ Wg, const float* __restrict__ Wu,
    const float* __restrict__ Wd)
{
    if (blockIdx.x == 0 && blockIdx.y == 0 && threadIdx.x < NEXP)
        g_cnt[threadIdx.x] = 0;
    int seg = blockIdx.y;
    size_t i = ((size_t)blockIdx.x * 256 + threadIdx.x) * 4;
    const float* s = (seg == 0) ? Wg : (seg == 1) ? Wu : Wd;
    __half* d = (seg == 0) ? g_wgh : (seg == 1) ? g_wuh : g_wdh;
    float4 v = *(const float4*)(s + i);
    __half2 lo = __floats2half2_rn(v.x, v.y);
    __half2 hi = __floats2half2_rn(v.z, v.w);
    *(uint2*)(d + i) = make_uint2(*(uint32_t*)&lo, *(uint32_t*)&hi);
}

// ---------------- router (fp32-exact) + x->fp16 ----------------
__global__ __launch_bounds__(128) void router_kernel(
    const float* __restrict__ x, const float* __restrict__ Wr)
{
    int t = blockIdx.x * 4 + (threadIdx.x >> 5);
    int lane = threadIdx.x & 31;
    const float* xr = x + (size_t)t * HDIM;
    float acc[NEXP];
#pragma unroll
    for (int e = 0; e < NEXP; e++) acc[e] = 0.0f;
    for (int h = lane; h < HDIM; h += 32) {
        float xv = xr[h];
        g_xh[(size_t)t * HDIM + h] = __float2half_rn(xv);
        const float4* wr4 = (const float4*)(Wr + (size_t)h * NEXP);
        float4 w0 = wr4[0], w1 = wr4[1];
        acc[0] = fmaf(xv, w0.x, acc[0]); acc[1] = fmaf(xv, w0.y, acc[1]);
        acc[2] = fmaf(xv, w0.z, acc[2]); acc[3] = fmaf(xv, w0.w, acc[3]);
        acc[4] = fmaf(xv, w1.x, acc[4]); acc[5] = fmaf(xv, w1.y, acc[5]);
        acc[6] = fmaf(xv, w1.z, acc[6]); acc[7] = fmaf(xv, w1.w, acc[7]);
    }
#pragma unroll
    for (int e = 0; e < NEXP; e++)
#pragma unroll
        for (int o = 16; o > 0; o >>= 1)
            acc[e] += __shfl_xor_sync(0xFFFFFFFFu, acc[e], o);
    if (lane == 0) {
        float m = acc[0];
#pragma unroll
        for (int e = 1; e < NEXP; e++) m = fmaxf(m, acc[e]);
        float p[NEXP];
#pragma unroll
        for (int e = 0; e < NEXP; e++) p[e] = expf(acc[e] - m);
        int i0 = 0;
#pragma unroll
        for (int e = 1; e < NEXP; e++) if (p[e] > p[i0]) i0 = e;
        int i1 = (i0 == 0) ? 1 : 0;
#pragma unroll
        for (int e = 0; e < NEXP; e++) if (e != i0 && p[e] > p[i1]) i1 = e;
        float s = p[i0] + p[i1];
        int p0 = atomicAdd(&g_cnt[i0], 1);
        g_tok[i0 * MAXP + p0] = t; g_wt[i0 * MAXP + p0] = p[i0] / s;
        g_pair[t * 2 + 0] = (i0 << 12) | p0;
        int p1 = atomicAdd(&g_cnt[i1], 1);
        g_tok[i1 * MAXP + p1] = t; g_wt[i1 * MAXP + p1] = p[i1] / s;
        g_pair[t * 2 + 1] = (i1 << 12) | p1;
    }
}

// =====================================================================
// gate+up GEMM + SwiGLU. Block 128m x 128n' (8-col chunks alternate
// gate/up), BK=32, 256 threads, 8 warps (2m x 4n), warp 64x32.
// cp.async 4-stage; ALL stage LDSMs hoisted before the MMA block.
// =====================================================================
__global__ __launch_bounds__(256, 2) void mg_gateup()
{
    extern __shared__ char smraw[];
    uint32_t sb = smem_u32(smraw);
    int e, m0, gbase, cnt;
    if (!tile_map(blockIdx.x, e, m0, gbase, cnt)) return;
    int f0 = blockIdx.y * 64;

    int tid = threadIdx.x, lane = tid & 31, wid = tid >> 5;
    int wmi = wid >> 2, wni = wid & 3;
    int lr = lane >> 2, l3 = lane & 3;

    int*   stok = (int*)(smraw + 4 * STGB);
    float* swt  = (float*)(smraw + 4 * STGB + 512);
    if (tid < 128) {
        int r = m0 + tid, rc = min(r, cnt - 1);
        stok[tid] = g_tok[e * MAXP + rc];
        swt[tid]  = (r < cnt) ? g_wt[e * MAXP + rc] : 0.0f;
    }
    __syncthreads();

    int am = tid & 127, ac0 = tid >> 7;
    const __half* arow = g_xh + (size_t)stok[am] * HDIM;
    int bk = tid & 31, cb0 = tid >> 5;
    const __half* wsel = ((cb0 & 1) ? g_wuh : g_wgh) + (size_t)e * HDIM * FDIM
                        + (size_t)bk * FDIM + f0 + (cb0 >> 1) * 8;

    auto ISSUE = [&](int s) {
        int kb = s * 32;
        uint32_t Ab = sb + (s & 3) * STGB;
        uint32_t Bb = Ab + 8192;
        cpa16(Ab + ((ac0)     * 128 + am) * 16, arow + kb + ac0 * 8);
        cpa16(Ab + ((ac0 + 2) * 128 + am) * 16, arow + kb + (ac0 + 2) * 8);
        cpa16(Bb + ((cb0)     * 32 + bk) * 16, wsel + (size_t)kb * FDIM);
        cpa16(Bb + ((cb0 + 8) * 32 + bk) * 16, wsel + (size_t)kb * FDIM + 32);
    };

    float c[4][4][4];
#pragma unroll
    for (int a = 0; a < 4; a++)
#pragma unroll
        for (int b = 0; b < 4; b++)
#pragma unroll
            for (int k = 0; k < 4; k++) c[a][b][k] = 0.0f;

    const int NS = HDIM / 32;
    ISSUE(0); CPCOMMIT();
    ISSUE(1); CPCOMMIT();
    ISSUE(2); CPCOMMIT();

    uint32_t aoff = (uint32_t)((lane >> 4) * 128 + wmi * 64 + (lane & 15)) * 16;
    uint32_t boff = (uint32_t)((wni * 4 + (lane >> 4)) * 32 + (lane & 15)) * 16;

    for (int s = 0; s < NS; s++) {
        CPWAIT2();
        __syncthreads();
        if (s + 3 < NS) ISSUE(s + 3);
        CPCOMMIT();
        uint32_t Ab = sb + (s & 3) * STGB;
        uint32_t Bb = Ab + 8192;
        // hoisted fragment loads for BOTH kk halves
        uint32_t a[2][4][4], b[2][2][4];
#pragma unroll
        for (int kk = 0; kk < 2; kk++) {
#pragma unroll
            for (int mt = 0; mt < 4; mt++)
                LDSM4(a[kk][mt], Ab + aoff + (kk * 2 * 128 + mt * 16) * 16);
#pragma unroll
            for (int bt = 0; bt < 2; bt++)
                LDSM4T(b[kk][bt], Bb + boff + (bt * 2 * 32 + kk * 16) * 16);
        }
#pragma unroll
        for (int kk = 0; kk < 2; kk++)
#pragma unroll
            for (int nt = 0; nt < 4; nt++) {
                uint32_t b0 = b[kk][nt >> 1][(nt & 1) * 2];
                uint32_t b1 = b[kk][nt >> 1][(nt & 1) * 2 + 1];
#pragma unroll
                for (int mt = 0; mt < 4; mt++)
                    MMA16(c[mt][nt], a[kk][mt][0], a[kk][mt][1], a[kk][mt][2], a[kk][mt][3], b0, b1);
            }
    }

    // epilogue: nt even = gate, nt odd = up
#pragma unroll
    for (int mt = 0; mt < 4; mt++)
#pragma unroll
        for (int rr = 0; rr < 2; rr++) {
            int row = wmi * 64 + mt * 16 + lr + rr * 8;
            if (m0 + row < cnt) {
                float w = swt[row];
                __half* dst = g_acth + (size_t)(gbase + m0 + row) * FDIM + f0 + wni * 16 + 2 * l3;
#pragma unroll
                for (int j = 0; j < 2; j++) {
                    float gv0 = c[mt][2 * j][rr * 2],     gv1 = c[mt][2 * j][rr * 2 + 1];
                    float uv0 = c[mt][2 * j + 1][rr * 2], uv1 = c[mt][2 * j + 1][rr * 2 + 1];
                    float o0 = w * (gv0 / (1.0f + expf(-gv0))) * uv0;
                    float o1 = w * (gv1 / (1.0f + expf(-gv1))) * uv1;
                    *(__half2*)(dst + j * 8) = __floats2half2_rn(o0, o1);
                }
            }
        }
}

// =====================================================================
// down GEMM. Block 128m x 128h, BK=32, 256 threads, warp 64x32.
// =====================================================================
__global__ __launch_bounds__(256, 2) void mg_down()
{
    extern __shared__ char smraw[];
    uint32_t sb = smem_u32(smraw);
    int e, m0, gbase, cnt;
    if (!tile_map(blockIdx.x, e, m0, gbase, cnt)) return;
    int h0 = blockIdx.y * 128;

    int tid = threadIdx.x, lane = tid & 31, wid = tid >> 5;
    int wmi = wid >> 2, wni = wid & 3;
    int lr = lane >> 2, l3 = lane & 3;

    int am = tid & 127, ac0 = tid >> 7;
    const __half* arow = g_acth + (size_t)(gbase + min(m0 + am, cnt - 1)) * FDIM;
    int bk = tid & 31, cb0 = tid >> 5;
    const __half* wsel = g_wdh + (size_t)e * FDIM * HDIM + (size_t)bk * HDIM + h0 + cb0 * 8;

    auto ISSUE = [&](int s) {
        int kb = s * 32;
        uint32_t Ab = sb + (s & 3) * STGB;
        uint32_t Bb = Ab + 8192;
        cpa16(Ab + ((ac0)     * 128 + am) * 16, arow + kb + ac0 * 8);
        cpa16(Ab + ((ac0 + 2) * 128 + am) * 16, arow + kb + (ac0 + 2) * 8);
        cpa16(Bb + ((cb0)     * 32 + bk) * 16, wsel + (size_t)kb * HDIM);
        cpa16(Bb + ((cb0 + 8) * 32 + bk) * 16, wsel + (size_t)kb * HDIM + 64);
    };

    float c[4][4][4];
#pragma unroll
    for (int a = 0; a < 4; a++)
#pragma unroll
        for (int b = 0; b < 4; b++)
#pragma unroll
            for (int k = 0; k < 4; k++) c[a][b][k] = 0.0f;

    const int NS = FDIM / 32;
    ISSUE(0); CPCOMMIT();
    ISSUE(1); CPCOMMIT();
    ISSUE(2); CPCOMMIT();

    uint32_t aoff = (uint32_t)((lane >> 4) * 128 + wmi * 64 + (lane & 15)) * 16;
    uint32_t boff = (uint32_t)((wni * 4 + (lane >> 4)) * 32 + (lane & 15)) * 16;

    for (int s = 0; s < NS; s++) {
        CPWAIT2();
        __syncthreads();
        if (s + 3 < NS) ISSUE(s + 3);
        CPCOMMIT();
        uint32_t Ab = sb + (s & 3) * STGB;
        uint32_t Bb = Ab + 8192;
        uint32_t a[2][4][4], b[2][2][4];
#pragma unroll
        for (int kk = 0; kk < 2; kk++) {
#pragma unroll
            for (int mt = 0; mt < 4; mt++)
                LDSM4(a[kk][mt], Ab + aoff + (kk * 2 * 128 + mt * 16) * 16);
#pragma unroll
            for (int bt = 0; bt < 2; bt++)
                LDSM4T(b[kk][bt], Bb + boff + (bt * 2 * 32 + kk * 16) * 16);
        }
#pragma unroll
        for (int kk = 0; kk < 2; kk++)
#pragma unroll
            for (int nt = 0; nt < 4; nt++) {
                uint32_t b0 = b[kk][nt >> 1][(nt & 1) * 2];
                uint32_t b1 = b[kk][nt >> 1][(nt & 1) * 2 + 1];
#pragma unroll
                for (int mt = 0; mt < 4; mt++)
                    MMA16(c[mt][nt], a[kk][mt][0], a[kk][mt][1], a[kk][mt][2], a[kk][mt][3], b0, b1);
            }
    }

#pragma unroll
    for (int mt = 0; mt < 4; mt++)
#pragma unroll
        for (int rr = 0; rr < 2; rr++) {
            int row = wmi * 64 + mt * 16 + lr + rr * 8;
            if (m0 + row < cnt) {
                float* dst = g_dout + (size_t)(gbase + m0 + row) * HDIM + h0 + wni * 32 + 2 * l3;
#pragma unroll
                for (int nt = 0; nt < 4; nt++)
                    *(float2*)(dst + nt * 8) =
                        make_float2(c[mt][nt][rr * 2], c[mt][nt][rr * 2 + 1]);
            }
        }
}

// ---------------- combine (offsets computed inline) ----------------
__global__ __launch_bounds__(256) void combine_kernel(float* __restrict__ out)
{
    int idx = blockIdx.x * blockDim.x + threadIdx.x;
    int t = idx >> 8;
    int hq = (idx & 255) * 4;
    int v0 = g_pair[t * 2 + 0], v1 = g_pair[t * 2 + 1];
    int e0 = v0 >> 12, e1 = v1 >> 12;
    int off0 = 0, off1 = 0;
#pragma unroll
    for (int i = 0; i < NEXP; i++) {
        int ci = g_cnt[i];
        if (i < e0) off0 += ci;
        if (i < e1) off1 += ci;
    }
    int gi0 = off0 + (v0 & (MAXP - 1));
    int gi1 = off1 + (v1 & (MAXP - 1));
    float4 a = *(const float4*)(g_dout + (size_t)gi0 * HDIM + hq);
    float4 b = *(const float4*)(g_dout + (size_t)gi1 * HDIM + hq);
    float4 o = {a.x + b.x, a.y + b.y, a.z + b.z, a.w + b.w};
    *(float4*)(out + (size_t)t * HDIM + hq) = o;
}

// ---------------- launch ----------------
extern "C" void kernel_launch(void* const* d_in, const int* in_sizes, int n_in,
                              void* d_out, int out_size)
{
    const float* x  = (const float*)d_in[0];
    const float* Wr = (const float*)d_in[1];
    const float* Wg = (const float*)d_in[2];
    const float* Wu = (const float*)d_in[3];
    const float* Wd = (const float*)d_in[4];
    float* out = (float*)d_out;

    cudaFuncSetAttribute(mg_gateup, cudaFuncAttributeMaxDynamicSharedMemorySize, GEMM_SMEM);
    cudaFuncSetAttribute(mg_down,   cudaFuncAttributeMaxDynamicSharedMemorySize, GEMM_SMEM);

    wconv_kernel<<<dim3(WELEM / 1024, 3), 256>>>(Wg, Wu, Wd);
    router_kernel<<<T_TOK / 4, 128>>>(x, Wr);

    dim3 gg(72, FDIM / 64);
    mg_gateup<<<gg, 256, GEMM_SMEM>>>();

    dim3 gd(72, HDIM / 128);
    mg_down<<<gd, 256, GEMM_SMEM>>>();

    combine_kernel<<<(T_TOK * HDIM / 4) / 256, 256>>>(out);
}

// round 11
// speedup vs baseline: 1.1056x; 1.0650x over previous
#include <cuda_runtime.h>
#include <cuda_fp16.h>
#include <math.h>
#include <stdint.h>

#define T_TOK 4096
#define HDIM 1024
#define FDIM 512
#define NEXP 8
#define MAXP 4096

// ---------------- device scratch ----------------
__device__ int    g_cnt[NEXP];
__device__ int    g_tok[NEXP * MAXP];
__device__ float  g_wt [NEXP * MAXP];
__device__ int    g_pair[T_TOK * 2];
__device__ __half g_xh   [T_TOK * HDIM];
__device__ __half g_acth [T_TOK * 2 * FDIM];
__device__ __half g_douth[T_TOK * 2 * HDIM];

#define MMA16(c, a0, a1, a2, a3, b0, b1) \
    asm volatile("mma.sync.aligned.m16n8k16.row.col.f32.f16.f16.f32 " \
        "{%0,%1,%2,%3},{%4,%5,%6,%7},{%8,%9},{%0,%1,%2,%3};" \
        : "+f"((c)[0]), "+f"((c)[1]), "+f"((c)[2]), "+f"((c)[3]) \
        : "r"(a0), "r"(a1), "r"(a2), "r"(a3), "r"(b0), "r"(b1))

__device__ __forceinline__ uint32_t h2u(__half2 h) {
    uint32_t u; asm("mov.b32 %0, %1;" : "=r"(u) : "r"(*(uint32_t*)&h)); return u;
}

// smem (uint2 units): A 8q x 132m, B 8q x 132n, per buffer 2112 uint2
#define QST 132
#define BUF2 2112
#define AOFF(b) ((b) * BUF2)
#define BOFF(b) ((b) * BUF2 + 8 * QST)
#define META2 (2 * BUF2)
#define GEMM_SMEM (2 * BUF2 * 8 + 1024)

// map flat tile -> (expert, m0, gbase, cnt); tiles are 128 rows
__device__ __forceinline__ bool tile_map(int tile, int& e, int& m0, int& gbase, int& cnt) {
    int acc = 0, off = 0;
#pragma unroll
    for (int i = 0; i < NEXP; i++) {
        int c = g_cnt[i];
        int nt = (c + 127) >> 7;
        if (tile < acc + nt) { e = i; m0 = (tile - acc) << 7; gbase = off; cnt = c; return true; }
        acc += nt; off += c;
    }
    return false;
}

// ---------------- zero counters ----------------
__global__ void zero_cnt_kernel() { if (threadIdx.x < NEXP) g_cnt[threadIdx.x] = 0; }

// ---------------- router v2: smem-cached Wr, 32 tokens per block ----------------
__global__ __launch_bounds__(256) void router_kernel(
    const float* __restrict__ x, const float* __restrict__ Wr)
{
    __shared__ float s_wrT[NEXP * HDIM];   // 32KB, expert-major
    int tid = threadIdx.x;
#pragma unroll
    for (int j = 0; j < 8; j++) {
        int idx = (j * 256 + tid) * 4;
        float4 v = *(const float4*)(Wr + idx);
        s_wrT[((idx + 0) & 7) * HDIM + ((idx + 0) >> 3)] = v.x;
        s_wrT[((idx + 1) & 7) * HDIM + ((idx + 1) >> 3)] = v.y;
        s_wrT[((idx + 2) & 7) * HDIM + ((idx + 2) >> 3)] = v.z;
        s_wrT[((idx + 3) & 7) * HDIM + ((idx + 3) >> 3)] = v.w;
    }
    __syncthreads();

    int lane = tid & 31, wid = tid >> 5;
    for (int tt = 0; tt < 4; tt++) {
        int t = blockIdx.x * 32 + wid * 4 + tt;
        const float* xr = x + (size_t)t * HDIM;
        float acc[NEXP];
#pragma unroll
        for (int e = 0; e < NEXP; e++) acc[e] = 0.0f;
        for (int h = lane; h < HDIM; h += 32) {
            float xv = xr[h];
            g_xh[(size_t)t * HDIM + h] = __float2half_rn(xv);
#pragma unroll
            for (int e = 0; e < NEXP; e++)
                acc[e] = fmaf(xv, s_wrT[e * HDIM + h], acc[e]);
        }
#pragma unroll
        for (int e = 0; e < NEXP; e++)
#pragma unroll
            for (int o = 16; o > 0; o >>= 1)
                acc[e] += __shfl_xor_sync(0xFFFFFFFFu, acc[e], o);
        if (lane == 0) {
            float m = acc[0];
#pragma unroll
            for (int e = 1; e < NEXP; e++) m = fmaxf(m, acc[e]);
            float p[NEXP];
#pragma unroll
            for (int e = 0; e < NEXP; e++) p[e] = expf(acc[e] - m);
            int i0 = 0;
#pragma unroll
            for (int e = 1; e < NEXP; e++) if (p[e] > p[i0]) i0 = e;
            int i1 = (i0 == 0) ? 1 : 0;
#pragma unroll
            for (int e = 0; e < NEXP; e++) if (e != i0 && p[e] > p[i1]) i1 = e;
            float s = p[i0] + p[i1];
            int p0 = atomicAdd(&g_cnt[i0], 1);
            g_tok[i0 * MAXP + p0] = t; g_wt[i0 * MAXP + p0] = p[i0] / s;
            g_pair[t * 2 + 0] = (i0 << 12) | p0;
            int p1 = atomicAdd(&g_cnt[i1], 1);
            g_tok[i1 * MAXP + p1] = t; g_wt[i1 * MAXP + p1] = p[i1] / s;
            g_pair[t * 2 + 1] = (i1 << 12) | p1;
        }
    }
}

// =====================================================================
// gate+up fp16 GEMM + SwiGLU. Block 128m x 128n' (n' 16-interleaved
// gate/up), BK=32, 256 threads, 8 warps (2m x 4n), warp tile 64x32.
// =====================================================================
__global__ __launch_bounds__(256, 2) void mg_gateup(
    const float* __restrict__ Wg,
    const float* __restrict__ Wu)
{
    extern __shared__ uint2 sm2[];
    int e, m0, gbase, cnt;
    if (!tile_map(blockIdx.x, e, m0, gbase, cnt)) return;
    int f0 = blockIdx.y * 64;

    int tid = threadIdx.x, lane = tid & 31, wid = tid >> 5;
    int wmi = wid >> 2, wni = wid & 3;
    int lr = lane >> 2, l3 = lane & 3;

    int*   stok = (int*)(sm2 + META2);
    float* swt  = (float*)(sm2 + META2 + 64);
    if (tid < 128) {
        int r = m0 + tid, rc = min(r, cnt - 1);
        stok[tid] = g_tok[e * MAXP + rc];
        swt[tid]  = (r < cnt) ? g_wt[e * MAXP + rc] : 0.0f;
    }
    __syncthreads();

    int am = tid >> 1, kh = (tid & 1) * 16;
    const __half* arow = g_xh + (size_t)stok[am] * HDIM + kh;
    int aqb = (tid & 1) * 4;
    int bp = (wid & 3) + 8 * (wid >> 2);
    int n4 = lane * 4;
    int bmat = (n4 >> 4) & 1;
    int bf = ((n4 >> 5) << 4) + (((n4 >> 3) & 1) << 3) + (n4 & 7);
    const float* wsel = (bmat ? Wu : Wg) + (size_t)e * HDIM * FDIM + f0 + bf;

    uint4 au0, au1;
    float4 bv0, bv1, bv2, bv3;
    auto LOADG = [&](int s) {
        int kb = s * 32;
        const uint4* ap = (const uint4*)(arow + kb);
        au0 = ap[0]; au1 = ap[1];
        const float* bp0 = wsel + (size_t)(kb + 2 * bp) * FDIM;
        bv0 = *(const float4*)bp0;
        bv1 = *(const float4*)(bp0 + FDIM);
        bv2 = *(const float4*)(bp0 + 8 * FDIM);
        bv3 = *(const float4*)(bp0 + 9 * FDIM);
    };
    auto STORES = [&](int b) {
        uint2* A = sm2 + AOFF(b);
        uint2* B = sm2 + BOFF(b);
        const uint32_t* a0 = (const uint32_t*)&au0;
        const uint32_t* a1 = (const uint32_t*)&au1;
#pragma unroll
        for (int j = 0; j < 4; j++)
            A[(aqb + j) * QST + am] = make_uint2(a0[j], a1[j]);
        const float* v0 = (const float*)&bv0;
        const float* v1 = (const float*)&bv1;
        const float* v2 = (const float*)&bv2;
        const float* v3 = (const float*)&bv3;
#pragma unroll
        for (int j = 0; j < 4; j++) {
            uint32_t lo = h2u(__floats2half2_rn(v0[j], v1[j]));
            uint32_t hi = h2u(__floats2half2_rn(v2[j], v3[j]));
            B[wid * QST + n4 + j] = make_uint2(lo, hi);
        }
    };

    float c[4][4][4];
#pragma unroll
    for (int a = 0; a < 4; a++)
#pragma unroll
        for (int b = 0; b < 4; b++)
#pragma unroll
            for (int k = 0; k < 4; k++) c[a][b][k] = 0.0f;

    LOADG(0); STORES(0);
    const int NS = HDIM / 32;
    for (int s = 0; s < NS; s++) {
        __syncthreads();
        if (s + 1 < NS) LOADG(s + 1);
        uint2* A = sm2 + AOFF(s & 1);
        uint2* B = sm2 + BOFF(s & 1);
#pragma unroll
        for (int kk = 0; kk < 2; kk++) {
            int q = kk * 4 + l3;
            uint2 af[4], ah[4];
#pragma unroll
            for (int mt = 0; mt < 4; mt++) {
                int m = wmi * 64 + mt * 16 + lr;
                af[mt] = A[q * QST + m];
                ah[mt] = A[q * QST + m + 8];
            }
#pragma unroll
            for (int nt = 0; nt < 4; nt++) {
                uint2 b = B[q * QST + wni * 32 + nt * 8 + lr];
#pragma unroll
                for (int mt = 0; mt < 4; mt++)
                    MMA16(c[mt][nt], af[mt].x, ah[mt].x, af[mt].y, ah[mt].y, b.x, b.y);
            }
        }
        if (s + 1 < NS) STORES((s + 1) & 1);
    }

    // epilogue: nt 0,1 gate / nt 2,3 up at f = f0 + wni*16 + (nt&1)*8 + 2*l3
#pragma unroll
    for (int mt = 0; mt < 4; mt++)
#pragma unroll
        for (int rr = 0; rr < 2; rr++) {
            int row = wmi * 64 + mt * 16 + lr + rr * 8;
            if (m0 + row < cnt) {
                float w = swt[row];
                __half* dst = g_acth + (size_t)(gbase + m0 + row) * FDIM + f0 + wni * 16 + 2 * l3;
#pragma unroll
                for (int ntl = 0; ntl < 2; ntl++) {
                    float gv0 = c[mt][ntl][rr * 2],     gv1 = c[mt][ntl][rr * 2 + 1];
                    float uv0 = c[mt][ntl + 2][rr * 2], uv1 = c[mt][ntl + 2][rr * 2 + 1];
                    float o0 = w * (gv0 / (1.0f + expf(-gv0))) * uv0;
                    float o1 = w * (gv1 / (1.0f + expf(-gv1))) * uv1;
                    *(__half2*)(dst + ntl * 8) = __floats2half2_rn(o0, o1);
                }
            }
        }
}

// =====================================================================
// down fp16 GEMM. Block 128m x 128h, BK=32, 256 threads, warp 64x32.
// =====================================================================
__global__ __launch_bounds__(256, 2) void mg_down(const float* __restrict__ Wd)
{
    extern __shared__ uint2 sm2[];
    int e, m0, gbase, cnt;
    if (!tile_map(blockIdx.x, e, m0, gbase, cnt)) return;
    int h0 = blockIdx.y * 128;

    int tid = threadIdx.x, lane = tid & 31, wid = tid >> 5;
    int wmi = wid >> 2, wni = wid & 3;
    int lr = lane >> 2, l3 = lane & 3;

    int am = tid >> 1, kh = (tid & 1) * 16;
    const __half* arow = g_acth + (size_t)(gbase + min(m0 + am, cnt - 1)) * FDIM + kh;
    int aqb = (tid & 1) * 4;
    int bp = (wid & 3) + 8 * (wid >> 2);
    int n4 = lane * 4;
    const float* wsel = Wd + (size_t)e * FDIM * HDIM + h0 + n4;

    uint4 au0, au1;
    float4 bv0, bv1, bv2, bv3;
    auto LOADG = [&](int s) {
        int kb = s * 32;
        const uint4* ap = (const uint4*)(arow + kb);
        au0 = ap[0]; au1 = ap[1];
        const float* bp0 = wsel + (size_t)(kb + 2 * bp) * HDIM;
        bv0 = *(const float4*)bp0;
        bv1 = *(const float4*)(bp0 + HDIM);
        bv2 = *(const float4*)(bp0 + 8 * HDIM);
        bv3 = *(const float4*)(bp0 + 9 * HDIM);
    };
    auto STORES = [&](int b) {
        uint2* A = sm2 + AOFF(b);
        uint2* B = sm2 + BOFF(b);
        const uint32_t* a0 = (const uint32_t*)&au0;
        const uint32_t* a1 = (const uint32_t*)&au1;
#pragma unroll
        for (int j = 0; j < 4; j++)
            A[(aqb + j) * QST + am] = make_uint2(a0[j], a1[j]);
        const float* v0 = (const float*)&bv0;
        const float* v1 = (const float*)&bv1;
        const float* v2 = (const float*)&bv2;
        const float* v3 = (const float*)&bv3;
#pragma unroll
        for (int j = 0; j < 4; j++) {
            uint32_t lo = h2u(__floats2half2_rn(v0[j], v1[j]));
            uint32_t hi = h2u(__floats2half2_rn(v2[j], v3[j]));
            B[wid * QST + n4 + j] = make_uint2(lo, hi);
        }
    };

    float c[4][4][4];
#pragma unroll
    for (int a = 0; a < 4; a++)
#pragma unroll
        for (int b = 0; b < 4; b++)
#pragma unroll
            for (int k = 0; k < 4; k++) c[a][b][k] = 0.0f;

    LOADG(0); STORES(0);
    const int NS = FDIM / 32;
    for (int s = 0; s < NS; s++) {
        __syncthreads();
        if (s + 1 < NS) LOADG(s + 1);
        uint2* A = sm2 + AOFF(s & 1);
        uint2* B = sm2 + BOFF(s & 1);
#pragma unroll
        for (int kk = 0; kk < 2; kk++) {
            int q = kk * 4 + l3;
            uint2 af[4], ah[4];
#pragma unroll
            for (int mt = 0; mt < 4; mt++) {
                int m = wmi * 64 + mt * 16 + lr;
                af[mt] = A[q * QST + m];
                ah[mt] = A[q * QST + m + 8];
            }
#pragma unroll
            for (int nt = 0; nt < 4; nt++) {
                uint2 b = B[q * QST + wni * 32 + nt * 8 + lr];
#pragma unroll
                for (int mt = 0; mt < 4; mt++)
                    MMA16(c[mt][nt], af[mt].x, ah[mt].x, af[mt].y, ah[mt].y, b.x, b.y);
            }
        }
        if (s + 1 < NS) STORES((s + 1) & 1);
    }

#pragma unroll
    for (int mt = 0; mt < 4; mt++)
#pragma unroll
        for (int rr = 0; rr < 2; rr++) {
            int row = wmi * 64 + mt * 16 + lr + rr * 8;
            if (m0 + row < cnt) {
                __half* dst = g_douth + (size_t)(gbase + m0 + row) * HDIM + h0 + wni * 32 + 2 * l3;
#pragma unroll
                for (int nt = 0; nt < 4; nt++)
                    *(__half2*)(dst + nt * 8) =
                        __floats2half2_rn(c[mt][nt][rr * 2], c[mt][nt][rr * 2 + 1]);
            }
        }
}

// ---------------- combine (offsets inline, fp16 sources) ----------------
__global__ __launch_bounds__(256) void combine_kernel(float* __restrict__ out)
{
    int idx = blockIdx.x * blockDim.x + threadIdx.x;
    int t = idx >> 8;
    int hq = (idx & 255) * 4;
    int v0 = g_pair[t * 2 + 0], v1 = g_pair[t * 2 + 1];
    int e0 = v0 >> 12, e1 = v1 >> 12;
    int off0 = 0, off1 = 0;
#pragma unroll
    for (int i = 0; i < NEXP; i++) {
        int ci = g_cnt[i];
        if (i < e0) off0 += ci;
        if (i < e1) off1 += ci;
    }
    size_t gi0 = (size_t)(off0 + (v0 & (MAXP - 1))) * HDIM + hq;
    size_t gi1 = (size_t)(off1 + (v1 & (MAXP - 1))) * HDIM + hq;
    uint2 ua = *(const uint2*)(g_douth + gi0);
    uint2 ub = *(const uint2*)(g_douth + gi1);
    __half2 a0 = *(__half2*)&ua.x, a1 = *(__half2*)&ua.y;
    __half2 b0 = *(__half2*)&ub.x, b1 = *(__half2*)&ub.y;
    float2 fa0 = __half22float2(a0), fa1 = __half22float2(a1);
    float2 fb0 = __half22float2(b0), fb1 = __half22float2(b1);
    float4 o = { fa0.x + fb0.x, fa0.y + fb0.y, fa1.x + fb1.x, fa1.y + fb1.y };
    *(float4*)(out + (size_t)t * HDIM + hq) = o;
}

// ---------------- launch ----------------
extern "C" void kernel_launch(void* const* d_in, const int* in_sizes, int n_in,
                              void* d_out, int out_size)
{
    const float* x  = (const float*)d_in[0];
    const float* Wr = (const float*)d_in[1];
    const float* Wg = (const float*)d_in[2];
    const float* Wu = (const float*)d_in[3];
    const float* Wd = (const float*)d_in[4];
    float* out = (float*)d_out;

    cudaFuncSetAttribute(mg_gateup, cudaFuncAttributeMaxDynamicSharedMemorySize, GEMM_SMEM);
    cudaFuncSetAttribute(mg_down,   cudaFuncAttributeMaxDynamicSharedMemorySize, GEMM_SMEM);

    zero_cnt_kernel<<<1, 32>>>();
    router_kernel<<<T_TOK / 32, 256>>>(x, Wr);

    dim3 gg(72, FDIM / 64);
    mg_gateup<<<gg, 256, GEMM_SMEM>>>(Wg, Wu);

    dim3 gd(72, HDIM / 128);
    mg_down<<<gd, 256, GEMM_SMEM>>>(Wd);

    combine_kernel<<<(T_TOK * HDIM / 4) / 256, 256>>>(out);
}

// round 12
// speedup vs baseline: 1.1172x; 1.0105x over previous
#include <cuda_runtime.h>
#include <cuda_fp16.h>
#include <math.h>
#include <stdint.h>

#define T_TOK 4096
#define HDIM 1024
#define FDIM 512
#define NEXP 8
#define MAXP 4096

// ---------------- device scratch ----------------
__device__ int    g_cnt[NEXP];
__device__ int    g_tok[NEXP * MAXP];
__device__ float  g_wt [NEXP * MAXP];
__device__ int    g_pair[T_TOK * 2];
__device__ __half g_xh  [T_TOK * HDIM];
__device__ __half g_acth[T_TOK * 2 * FDIM];
__device__ float  g_dout[T_TOK * 2 * HDIM];

#define MMA16(c, a0, a1, a2, a3, b0, b1) \
    asm volatile("mma.sync.aligned.m16n8k16.row.col.f32.f16.f16.f32 " \
        "{%0,%1,%2,%3},{%4,%5,%6,%7},{%8,%9},{%0,%1,%2,%3};" \
        : "+f"((c)[0]), "+f"((c)[1]), "+f"((c)[2]), "+f"((c)[3]) \
        : "r"(a0), "r"(a1), "r"(a2), "r"(a3), "r"(b0), "r"(b1))

__device__ __forceinline__ uint32_t h2u(__half2 h) {
    uint32_t u; asm("mov.b32 %0, %1;" : "=r"(u) : "r"(*(uint32_t*)&h)); return u;
}
// B column swizzle: breaks STS bank conflicts, preserves conflict-free reads
__device__ __forceinline__ int bswz(int col) { return col ^ ((col >> 4) & 3); }

// smem (uint2 units): A 8q x 132m, B 8q x 260n', per buffer 3136 uint2
#define QSTA 132
#define QSTB 260
#define ABUF2 (8 * QSTA)
#define BBUF2 (8 * QSTB)
#define BUF2  (ABUF2 + BBUF2)
#define AOFF(b) ((b) * BUF2)
#define BOFF(b) ((b) * BUF2 + ABUF2)
#define META2 (2 * BUF2)
#define GEMM_SMEM (2 * BUF2 * 8 + 1024)

// map flat tile -> (expert, m0, gbase, cnt); tiles are 128 rows
__device__ __forceinline__ bool tile_map(int tile, int& e, int& m0, int& gbase, int& cnt) {
    int acc = 0, off = 0;
#pragma unroll
    for (int i = 0; i < NEXP; i++) {
        int c = g_cnt[i];
        int nt = (c + 127) >> 7;
        if (tile < acc + nt) { e = i; m0 = (tile - acc) << 7; gbase = off; cnt = c; return true; }
        acc += nt; off += c;
    }
    return false;
}

// ---------------- zero counters ----------------
__global__ void zero_cnt_kernel() { if (threadIdx.x < NEXP) g_cnt[threadIdx.x] = 0; }

// ---------------- router (fp32-exact, R7-proven) + x->fp16 ----------------
__global__ __launch_bounds__(128) void router_kernel(
    const float* __restrict__ x, const float* __restrict__ Wr)
{
    int t = blockIdx.x * 4 + (threadIdx.x >> 5);
    int lane = threadIdx.x & 31;
    const float* xr = x + (size_t)t * HDIM;
    float acc[NEXP];
#pragma unroll
    for (int e = 0; e < NEXP; e++) acc[e] = 0.0f;
    for (int h = lane; h < HDIM; h += 32) {
        float xv = xr[h];
        g_xh[(size_t)t * HDIM + h] = __float2half_rn(xv);
        const float4* wr4 = (const float4*)(Wr + (size_t)h * NEXP);
        float4 w0 = wr4[0], w1 = wr4[1];
        acc[0] = fmaf(xv, w0.x, acc[0]); acc[1] = fmaf(xv, w0.y, acc[1]);
        acc[2] = fmaf(xv, w0.z, acc[2]); acc[3] = fmaf(xv, w0.w, acc[3]);
        acc[4] = fmaf(xv, w1.x, acc[4]); acc[5] = fmaf(xv, w1.y, acc[5]);
        acc[6] = fmaf(xv, w1.z, acc[6]); acc[7] = fmaf(xv, w1.w, acc[7]);
    }
#pragma unroll
    for (int e = 0; e < NEXP; e++)
#pragma unroll
        for (int o = 16; o > 0; o >>= 1)
            acc[e] += __shfl_xor_sync(0xFFFFFFFFu, acc[e], o);
    if (lane == 0) {
        float m = acc[0];
#pragma unroll
        for (int e = 1; e < NEXP; e++) m = fmaxf(m, acc[e]);
        float p[NEXP];
#pragma unroll
        for (int e = 0; e < NEXP; e++) p[e] = expf(acc[e] - m);
        int i0 = 0;
#pragma unroll
        for (int e = 1; e < NEXP; e++) if (p[e] > p[i0]) i0 = e;
        int i1 = (i0 == 0) ? 1 : 0;
#pragma unroll
        for (int e = 0; e < NEXP; e++) if (e != i0 && p[e] > p[i1]) i1 = e;
        float s = p[i0] + p[i1];
        int p0 = atomicAdd(&g_cnt[i0], 1);
        g_tok[i0 * MAXP + p0] = t; g_wt[i0 * MAXP + p0] = p[i0] / s;
        g_pair[t * 2 + 0] = (i0 << 12) | p0;
        int p1 = atomicAdd(&g_cnt[i1], 1);
        g_tok[i1 * MAXP + p1] = t; g_wt[i1 * MAXP + p1] = p[i1] / s;
        g_pair[t * 2 + 1] = (i1 << 12) | p1;
    }
}

// =====================================================================
// gate+up fp16 GEMM + SwiGLU. Block 128m x 256n' (16-col interleave of
// gate/up over 128 f), BK=32, 256 threads, 8 warps (2m x 4n),
// warp tile 64 x 64. Double-buffered register->smem staging.
// =====================================================================
__global__ __launch_bounds__(256, 1) void mg_gateup(
    const float* __restrict__ Wg,
    const float* __restrict__ Wu)
{
    extern __shared__ uint2 sm2[];
    int e, m0, gbase, cnt;
    if (!tile_map(blockIdx.x, e, m0, gbase, cnt)) return;
    int f0 = blockIdx.y * 128;

    int tid = threadIdx.x, lane = tid & 31, wid = tid >> 5;
    int wmi = wid >> 2, wni = wid & 3;
    int lr = lane >> 2, l3 = lane & 3;

    int*   stok = (int*)(sm2 + META2);
    float* swt  = (float*)(sm2 + META2 + 64);
    if (tid < 128) {
        int r = m0 + tid, rc = min(r, cnt - 1);
        stok[tid] = g_tok[e * MAXP + rc];
        swt[tid]  = (r < cnt) ? g_wt[e * MAXP + rc] : 0.0f;
    }
    __syncthreads();

    // A staging (identical to R7)
    int am = tid >> 1, kh = (tid & 1) * 16;
    const __half* arow = g_xh + (size_t)stok[am] * HDIM + kh;
    int aqb = (tid & 1) * 4;
    // B staging: 256 n' x 32 k per stage
    int bn4 = (tid & 63) * 4;           // n' 0..252
    int bkq = tid >> 6;                 // 0..3
    int bmat = (bn4 >> 4) & 1;
    int bf = ((bn4 >> 5) << 4) + (((bn4 >> 3) & 1) << 3) + (bn4 & 7);
    const float* wsel = (bmat ? Wu : Wg) + (size_t)e * HDIM * FDIM + f0 + bf;

    uint4 au0, au1;
    float4 bv[2][4];
    auto LOADG = [&](int s) {
        int kb = s * 32;
        const uint4* ap = (const uint4*)(arow + kb);
        au0 = ap[0]; au1 = ap[1];
#pragma unroll
        for (int g = 0; g < 2; g++) {
            int p = bkq + g * 8;
            const float* bp0 = wsel + (size_t)(kb + 2 * p) * FDIM;
            bv[g][0] = *(const float4*)bp0;
            bv[g][1] = *(const float4*)(bp0 + FDIM);
            bv[g][2] = *(const float4*)(bp0 + 8 * FDIM);
            bv[g][3] = *(const float4*)(bp0 + 9 * FDIM);
        }
    };
    auto STORES = [&](int b) {
        uint2* A = sm2 + AOFF(b);
        uint2* B = sm2 + BOFF(b);
        const uint32_t* a0 = (const uint32_t*)&au0;
        const uint32_t* a1 = (const uint32_t*)&au1;
#pragma unroll
        for (int j = 0; j < 4; j++)
            A[(aqb + j) * QSTA + am] = make_uint2(a0[j], a1[j]);
#pragma unroll
        for (int g = 0; g < 2; g++) {
            int q = bkq + g * 4;
            const float* v0 = (const float*)&bv[g][0];
            const float* v1 = (const float*)&bv[g][1];
            const float* v2 = (const float*)&bv[g][2];
            const float* v3 = (const float*)&bv[g][3];
#pragma unroll
            for (int j = 0; j < 4; j++) {
                uint32_t lo = h2u(__floats2half2_rn(v0[j], v1[j]));
                uint32_t hi = h2u(__floats2half2_rn(v2[j], v3[j]));
                B[q * QSTB + bswz(bn4 + j)] = make_uint2(lo, hi);
            }
        }
    };

    float c[4][8][4];
#pragma unroll
    for (int a = 0; a < 4; a++)
#pragma unroll
        for (int b = 0; b < 8; b++)
#pragma unroll
            for (int k = 0; k < 4; k++) c[a][b][k] = 0.0f;

    LOADG(0); STORES(0);
    const int NS = HDIM / 32;
    for (int s = 0; s < NS; s++) {
        __syncthreads();
        if (s + 1 < NS) LOADG(s + 1);
        uint2* A = sm2 + AOFF(s & 1);
        uint2* B = sm2 + BOFF(s & 1);
#pragma unroll
        for (int kk = 0; kk < 2; kk++) {
            int q = kk * 4 + l3;
            uint2 af[4], ah[4];
#pragma unroll
            for (int mt = 0; mt < 4; mt++) {
                int m = wmi * 64 + mt * 16 + lr;
                af[mt] = A[q * QSTA + m];
                ah[mt] = A[q * QSTA + m + 8];
            }
#pragma unroll
            for (int nt = 0; nt < 8; nt++) {
                uint2 b = B[q * QSTB + bswz(wni * 64 + nt * 8 + lr)];
#pragma unroll
                for (int mt = 0; mt < 4; mt++)
                    MMA16(c[mt][nt], af[mt].x, ah[mt].x, af[mt].y, ah[mt].y, b.x, b.y);
            }
        }
        if (s + 1 < NS) STORES((s + 1) & 1);
    }

    // epilogue: n' = wni*64 + nt*8 + 2*l3; gate nt in {0,1,4,5}, up = nt+2
#pragma unroll
    for (int mt = 0; mt < 4; mt++)
#pragma unroll
        for (int rr = 0; rr < 2; rr++) {
            int row = wmi * 64 + mt * 16 + lr + rr * 8;
            if (m0 + row < cnt) {
                float w = swt[row];
                __half* dst = g_acth + (size_t)(gbase + m0 + row) * FDIM + f0;
#pragma unroll
                for (int jj = 0; jj < 4; jj++) {
                    int ntg = (jj & 1) + (jj >> 1) * 4;            // 0,1,4,5
                    int fl = ((wni * 2 + (ntg >> 2)) << 4) + ((ntg & 1) << 3) + 2 * l3;
                    float gv0 = c[mt][ntg][rr * 2],     gv1 = c[mt][ntg][rr * 2 + 1];
                    float uv0 = c[mt][ntg + 2][rr * 2], uv1 = c[mt][ntg + 2][rr * 2 + 1];
                    float o0 = w * (gv0 / (1.0f + expf(-gv0))) * uv0;
                    float o1 = w * (gv1 / (1.0f + expf(-gv1))) * uv1;
                    *(__half2*)(dst + fl) = __floats2half2_rn(o0, o1);
                }
            }
        }
}

// =====================================================================
// down fp16 GEMM. Block 128m x 256h, BK=32, 256 threads, warp 64x64.
// fp32 output (R7-proven).
// =====================================================================
__global__ __launch_bounds__(256, 1) void mg_down(const float* __restrict__ Wd)
{
    extern __shared__ uint2 sm2[];
    int e, m0, gbase, cnt;
    if (!tile_map(blockIdx.x, e, m0, gbase, cnt)) return;
    int h0 = blockIdx.y * 256;

    int tid = threadIdx.x, lane = tid & 31, wid = tid >> 5;
    int wmi = wid >> 2, wni = wid & 3;
    int lr = lane >> 2, l3 = lane & 3;

    int am = tid >> 1, kh = (tid & 1) * 16;
    const __half* arow = g_acth + (size_t)(gbase + min(m0 + am, cnt - 1)) * FDIM + kh;
    int aqb = (tid & 1) * 4;
    int bn4 = (tid & 63) * 4;
    int bkq = tid >> 6;
    const float* wsel = Wd + (size_t)e * FDIM * HDIM + h0 + bn4;

    uint4 au0, au1;
    float4 bv[2][4];
    auto LOADG = [&](int s) {
        int kb = s * 32;
        const uint4* ap = (const uint4*)(arow + kb);
        au0 = ap[0]; au1 = ap[1];
#pragma unroll
        for (int g = 0; g < 2; g++) {
            int p = bkq + g * 8;
            const float* bp0 = wsel + (size_t)(kb + 2 * p) * HDIM;
            bv[g][0] = *(const float4*)bp0;
            bv[g][1] = *(const float4*)(bp0 + HDIM);
            bv[g][2] = *(const float4*)(bp0 + 8 * HDIM);
            bv[g][3] = *(const float4*)(bp0 + 9 * HDIM);
        }
    };
    auto STORES = [&](int b) {
        uint2* A = sm2 + AOFF(b);
        uint2* B = sm2 + BOFF(b);
        const uint32_t* a0 = (const uint32_t*)&au0;
        const uint32_t* a1 = (const uint32_t*)&au1;
#pragma unroll
        for (int j = 0; j < 4; j++)
            A[(aqb + j) * QSTA + am] = make_uint2(a0[j], a1[j]);
#pragma unroll
        for (int g = 0; g < 2; g++) {
            int q = bkq + g * 4;
            const float* v0 = (const float*)&bv[g][0];
            const float* v1 = (const float*)&bv[g][1];
            const float* v2 = (const float*)&bv[g][2];
            const float* v3 = (const float*)&bv[g][3];
#pragma unroll
            for (int j = 0; j < 4; j++) {
                uint32_t lo = h2u(__floats2half2_rn(v0[j], v1[j]));
                uint32_t hi = h2u(__floats2half2_rn(v2[j], v3[j]));
                B[q * QSTB + bswz(bn4 + j)] = make_uint2(lo, hi);
            }
        }
    };

    float c[4][8][4];
#pragma unroll
    for (int a = 0; a < 4; a++)
#pragma unroll
        for (int b = 0; b < 8; b++)
#pragma unroll
            for (int k = 0; k < 4; k++) c[a][b][k] = 0.0f;

    LOADG(0); STORES(0);
    const int NS = FDIM / 32;
    for (int s = 0; s < NS; s++) {
        __syncthreads();
        if (s + 1 < NS) LOADG(s + 1);
        uint2* A = sm2 + AOFF(s & 1);
        uint2* B = sm2 + BOFF(s & 1);
#pragma unroll
        for (int kk = 0; kk < 2; kk++) {
            int q = kk * 4 + l3;
            uint2 af[4], ah[4];
#pragma unroll
            for (int mt = 0; mt < 4; mt++) {
                int m = wmi * 64 + mt * 16 + lr;
                af[mt] = A[q * QSTA + m];
                ah[mt] = A[q * QSTA + m + 8];
            }
#pragma unroll
            for (int nt = 0; nt < 8; nt++) {
                uint2 b = B[q * QSTB + bswz(wni * 64 + nt * 8 + lr)];
#pragma unroll
                for (int mt = 0; mt < 4; mt++)
                    MMA16(c[mt][nt], af[mt].x, ah[mt].x, af[mt].y, ah[mt].y, b.x, b.y);
            }
        }
        if (s + 1 < NS) STORES((s + 1) & 1);
    }

#pragma unroll
    for (int mt = 0; mt < 4; mt++)
#pragma unroll
        for (int rr = 0; rr < 2; rr++) {
            int row = wmi * 64 + mt * 16 + lr + rr * 8;
            if (m0 + row < cnt) {
                float* dst = g_dout + (size_t)(gbase + m0 + row) * HDIM + h0 + wni * 64 + 2 * l3;
#pragma unroll
                for (int nt = 0; nt < 8; nt++)
                    *(float2*)(dst + nt * 8) =
                        make_float2(c[mt][nt][rr * 2], c[mt][nt][rr * 2 + 1]);
            }
        }
}

// ---------------- combine (fp32, inline offsets) ----------------
__global__ __launch_bounds__(256) void combine_kernel(float* __restrict__ out)
{
    int idx = blockIdx.x * blockDim.x + threadIdx.x;
    int t = idx >> 8;
    int hq = (idx & 255) * 4;
    int v0 = g_pair[t * 2 + 0], v1 = g_pair[t * 2 + 1];
    int e0 = v0 >> 12, e1 = v1 >> 12;
    int off0 = 0, off1 = 0;
#pragma unroll
    for (int i = 0; i < NEXP; i++) {
        int ci = g_cnt[i];
        if (i < e0) off0 += ci;
        if (i < e1) off1 += ci;
    }
    int gi0 = off0 + (v0 & (MAXP - 1));
    int gi1 = off1 + (v1 & (MAXP - 1));
    float4 a = *(const float4*)(g_dout + (size_t)gi0 * HDIM + hq);
    float4 b = *(const float4*)(g_dout + (size_t)gi1 * HDIM + hq);
    float4 o = {a.x + b.x, a.y + b.y, a.z + b.z, a.w + b.w};
    *(float4*)(out + (size_t)t * HDIM + hq) = o;
}

// ---------------- launch ----------------
extern "C" void kernel_launch(void* const* d_in, const int* in_sizes, int n_in,
                              void* d_out, int out_size)
{
    const float* x  = (const float*)d_in[0];
    const float* Wr = (const float*)d_in[1];
    const float* Wg = (const float*)d_in[2];
    const float* Wu = (const float*)d_in[3];
    const float* Wd = (const float*)d_in[4];
    float* out = (float*)d_out;

    cudaFuncSetAttribute(mg_gateup, cudaFuncAttributeMaxDynamicSharedMemorySize, GEMM_SMEM);
    cudaFuncSetAttribute(mg_down,   cudaFuncAttributeMaxDynamicSharedMemorySize, GEMM_SMEM);

    zero_cnt_kernel<<<1, 32>>>();
    router_kernel<<<T_TOK / 4, 128>>>(x, Wr);

    dim3 gg(72, FDIM / 128);   // 72 x 4, early-exit on unused tiles
    mg_gateup<<<gg, 256, GEMM_SMEM>>>(Wg, Wu);

    dim3 gd(72, HDIM / 256);   // 72 x 4
    mg_down<<<gd, 256, GEMM_SMEM>>>(Wd);

    combine_kernel<<<(T_TOK * HDIM / 4) / 256, 256>>>(out);
}